// round 15
// baseline (speedup 1.0000x reference)
#include <cuda_runtime.h>
#include <cuda_bf16.h>
#include <cstdint>

#define BB 128
#define SS 1024
#define EE 512
#define HH 512
#define GG 2048
#define BSH (128*1024*512)

// ---------------- device scratch ----------------
__device__ float    g_xg[(size_t)SS * BB * GG];     // 1 GiB Xg[t][b][g]
__device__ uint32_t g_esh[(size_t)BB * SS * 256];   // embed bf16x2 hi plane
__device__ uint32_t g_esl[(size_t)BB * SS * 256];   // embed lo plane
__device__ uint32_t g_wsh[2 * GG * 256];            // W_ih hi plane
__device__ uint32_t g_wsl[2 * GG * 256];
__device__ uint32_t g_hsh[2 * BB * 256];            // h hi plane, shuffled pairs, dbl buf
__device__ uint32_t g_hsl[2 * BB * 256];
__device__ float    g_c[BB * HH];
__device__ float    g_biasc[2 * GG];
__device__ int      g_perm[SS * BB];
__device__ int      g_cnt0[SS];
__device__ int      g_flat[1025 * 128];
__device__ int      g_total0_pad;
__device__ unsigned g_count;
__device__ unsigned g_release;

// ---------------- helpers ----------------
__device__ __forceinline__ void split2(float x, float y, uint32_t& h, uint32_t& l) {
    unsigned short hx = __bfloat16_as_ushort(__float2bfloat16(x));
    unsigned short hy = __bfloat16_as_ushort(__float2bfloat16(y));
    float fx = __bfloat162float(__ushort_as_bfloat16(hx));
    float fy = __bfloat162float(__ushort_as_bfloat16(hy));
    unsigned short lx = __bfloat16_as_ushort(__float2bfloat16(x - fx));
    unsigned short ly = __bfloat16_as_ushort(__float2bfloat16(y - fy));
    h = ((uint32_t)hy << 16) | hx;
    l = ((uint32_t)ly << 16) | lx;
}

__device__ __forceinline__ void mma16(float* d, uint32_t a0, uint32_t a1, uint32_t a2,
                                      uint32_t a3, uint32_t b0, uint32_t b1) {
    asm volatile(
        "mma.sync.aligned.m16n8k16.row.col.f32.bf16.bf16.f32 "
        "{%0,%1,%2,%3},{%4,%5,%6,%7},{%8,%9},{%0,%1,%2,%3};\n"
        : "+f"(d[0]), "+f"(d[1]), "+f"(d[2]), "+f"(d[3])
        : "r"(a0), "r"(a1), "r"(a2), "r"(a3), "r"(b0), "r"(b1));
}

__device__ __forceinline__ void cpa16(uint32_t dst, const void* src, uint32_t nbytes) {
    asm volatile("cp.async.cg.shared.global [%0], [%1], 16, %2;\n"
                 :: "r"(dst), "l"(src), "r"(nbytes));
}
#define CP_COMMIT() asm volatile("cp.async.commit_group;\n")
#define CP_WAIT(n)  asm volatile("cp.async.wait_group %0;\n" :: "n"(n))

__device__ __forceinline__ float sigm(float x) {
    return __fdividef(1.f, 1.f + __expf(-x));
}
__device__ __forceinline__ float bf_lo(uint32_t u) {
    return __bfloat162float(__ushort_as_bfloat16((unsigned short)(u & 0xffffu)));
}
__device__ __forceinline__ float bf_hi(uint32_t u) {
    return __bfloat162float(__ushort_as_bfloat16((unsigned short)(u >> 16)));
}

// ---------------- k_init ----------------
__global__ void k_init(const float* __restrict__ bih, const float* __restrict__ bhh,
                       const float* __restrict__ embed, const float* __restrict__ Wih) {
    int bx = blockIdx.x, tid = threadIdx.x;
    if (bx < 2048) {
        int p0 = bx * 256 + tid;
        const float2* e2 = (const float2*)embed;
#pragma unroll 4
        for (int j = 0; j < 64; j++) {
            int p = p0 + j * 524288;
            float2 v = __ldg(e2 + p);
            uint32_t h, l; split2(v.x, v.y, h, l);
            g_esh[p] = h; g_esl[p] = l;
        }
    } else if (bx < 2112) {
        int p0 = (bx - 2048) * 256 + tid;
        const float2* w2 = (const float2*)Wih;
#pragma unroll 4
        for (int j = 0; j < 64; j++) {
            int p = p0 + j * 16384;
            float2 v = __ldg(w2 + p);
            uint32_t h, l; split2(v.x, v.y, h, l);
            g_wsh[p] = h; g_wsl[p] = l;
        }
    } else {
        int i0 = (bx - 2112) * 256 + tid;
#pragma unroll
        for (int j = 0; j < 2; j++) { int i = i0 + j * 2048; g_biasc[i] = bih[i] + bhh[i]; }
#pragma unroll
        for (int j = 0; j < 32; j++) { int i = i0 + j * 2048; g_c[i] = 0.f; }
#pragma unroll
        for (int j = 0; j < 32; j++) { int i = i0 + j * 2048; g_hsh[i] = 0u; g_hsl[i] = 0u; }
        if (bx == 2112 && tid == 0) { g_count = 0u; g_release = 0u; }
    }
}

// ---------------- k_setup ----------------
__global__ void k_setup(const int* __restrict__ inp) {
    __shared__ int s[1024];
    int t = threadIdx.x;
    int i0 = 0, i1 = 128;
    for (int b = 0; b < 128; b++) {
        int v = inp[b * SS + t] & 1;
        if (!v) g_perm[t * 128 + i0++] = b;
        else    g_perm[t * 128 + --i1] = b;
    }
    g_cnt0[t] = i0;
    s[t] = i0;
    __syncthreads();
    for (int off = 1; off < 1024; off <<= 1) {
        int v = (t >= off) ? s[t - off] : 0;
        __syncthreads();
        s[t] += v;
        __syncthreads();
    }
    int tot0 = s[1023];
    int t0p = (tot0 + 127) & ~127;
    int base0 = s[t] - i0;
    int base1 = t0p + 128 * t - base0;
    for (int i = 0; i < i0; i++)
        g_flat[base0 + i] = (g_perm[t * 128 + i] << 10) | t;
    for (int i = i0; i < 128; i++)
        g_flat[base1 + (i - i0)] = (g_perm[t * 128 + i] << 10) | t;
    if (t == 0) g_total0_pad = t0p;
    int mid = t0p - tot0;
    if (t < mid) g_flat[tot0 + t] = -1;
    int fe = t0p + (SS * BB - tot0);
    int tail = 1025 * 128 - fe;
    if (t < tail) g_flat[fe + t] = -1;
}

// ---------------- phase 1 (unchanged from R12) ----------------
#define SMEM1 ((5120 + 5120 + 2560 + 2560 + 128) * 4)

__global__ __launch_bounds__(256) void k_phase1() {
    extern __shared__ uint32_t smu[];
    uint32_t* sAh = smu;
    uint32_t* sAl = sAh + 5120;
    uint32_t* sBh = sAl + 5120;
    uint32_t* sBl = sBh + 2560;
    int*      toks = (int*)(sBl + 2560);

    const int tid = threadIdx.x, lane = tid & 31, warp = tid >> 5;
    const int wm = warp & 3, wn = warp >> 2;
    const int m0 = blockIdx.y * 128, n0 = blockIdx.x * 64;

    if (tid < 128) toks[tid] = g_flat[m0 + tid];
    __syncthreads();
    const int cell = (m0 >= g_total0_pad) ? 1 : 0;
    const float* biasb = g_biasc + cell * GG;

    const int q = tid & 3;
    const int ra0 = tid >> 2, ra1 = 64 + ra0, rb = tid >> 2;
    const int tok0 = toks[ra0], tok1 = toks[ra1];
    const uint32_t szA0 = (tok0 >= 0) ? 16u : 0u;
    const uint32_t szA1 = (tok1 >= 0) ? 16u : 0u;
    const uint32_t* s0h = g_esh + (size_t)max(tok0, 0) * 256 + q * 4;
    const uint32_t* s0l = g_esl + (size_t)max(tok0, 0) * 256 + q * 4;
    const uint32_t* s1h = g_esh + (size_t)max(tok1, 0) * 256 + q * 4;
    const uint32_t* s1l = g_esl + (size_t)max(tok1, 0) * 256 + q * 4;
    const uint32_t* sbh = g_wsh + ((size_t)cell * GG + n0 + rb) * 256 + q * 4;
    const uint32_t* sbl = g_wsl + ((size_t)cell * GG + n0 + rb) * 256 + q * 4;

    const uint32_t aAh = (uint32_t)__cvta_generic_to_shared(sAh);
    const uint32_t aAl = (uint32_t)__cvta_generic_to_shared(sAl);
    const uint32_t aBh = (uint32_t)__cvta_generic_to_shared(sBh);
    const uint32_t aBl = (uint32_t)__cvta_generic_to_shared(sBl);
    const uint32_t dA0 = (ra0 * 20 + q * 4) * 4;
    const uint32_t dA1 = (ra1 * 20 + q * 4) * 4;
    const uint32_t dB  = (rb * 20 + q * 4) * 4;

    auto fill = [&](int s) {
        int buf = s & 1, ko = s * 16;
        uint32_t bo = buf * 2560 * 4, bo2 = buf * 1280 * 4;
        cpa16(aAh + bo + dA0, s0h + ko, szA0);
        cpa16(aAh + bo + dA1, s1h + ko, szA1);
        cpa16(aAl + bo + dA0, s0l + ko, szA0);
        cpa16(aAl + bo + dA1, s1l + ko, szA1);
        cpa16(aBh + bo2 + dB, sbh + ko, 16u);
        cpa16(aBl + bo2 + dB, sbl + ko, 16u);
        CP_COMMIT();
    };

    float d[2][4][4];
#pragma unroll
    for (int a = 0; a < 2; a++)
#pragma unroll
        for (int b = 0; b < 4; b++)
#pragma unroll
            for (int c = 0; c < 4; c++) d[a][b][c] = 0.f;

    const int cq = lane & 3, rq = lane >> 2;

    fill(0);
    for (int ks = 0; ks < 16; ks++) {
        if (ks < 15) { fill(ks + 1); CP_WAIT(1); }
        else         { CP_WAIT(0); }
        __syncthreads();
        const int buf = ks & 1;
        const uint32_t* Ah = sAh + buf * 2560;
        const uint32_t* Al = sAl + buf * 2560;
        const uint32_t* Bh = sBh + buf * 1280;
        const uint32_t* Bl = sBl + buf * 1280;
#pragma unroll
        for (int kc = 0; kc < 2; kc++) {
            int kb = kc * 8 + cq;
            uint32_t bh[4][2], bl[4][2];
#pragma unroll
            for (int nt = 0; nt < 4; nt++) {
                int n = wn * 32 + nt * 8 + rq;
                bh[nt][0] = Bh[n * 20 + kb]; bh[nt][1] = Bh[n * 20 + kb + 4];
                bl[nt][0] = Bl[n * 20 + kb]; bl[nt][1] = Bl[n * 20 + kb + 4];
            }
#pragma unroll
            for (int mt = 0; mt < 2; mt++) {
                int r = wm * 32 + mt * 16 + rq;
                uint32_t ah0 = Ah[r * 20 + kb],     ah1 = Ah[(r + 8) * 20 + kb];
                uint32_t ah2 = Ah[r * 20 + kb + 4], ah3 = Ah[(r + 8) * 20 + kb + 4];
                uint32_t al0 = Al[r * 20 + kb],     al1 = Al[(r + 8) * 20 + kb];
                uint32_t al2 = Al[r * 20 + kb + 4], al3 = Al[(r + 8) * 20 + kb + 4];
#pragma unroll
                for (int nt = 0; nt < 4; nt++) {
                    mma16(d[mt][nt], ah0, ah1, ah2, ah3, bh[nt][0], bh[nt][1]);
                    mma16(d[mt][nt], ah0, ah1, ah2, ah3, bl[nt][0], bl[nt][1]);
                    mma16(d[mt][nt], al0, al1, al2, al3, bh[nt][0], bh[nt][1]);
                }
            }
        }
        __syncthreads();
    }

#pragma unroll
    for (int mt = 0; mt < 2; mt++)
#pragma unroll
        for (int half = 0; half < 2; half++) {
            int r = wm * 32 + mt * 16 + rq + half * 8;
            int tok = toks[r];
            if (tok < 0) continue;
            int tt = tok & 1023, b = tok >> 10;
            size_t base = ((size_t)(tt * 128 + b)) * GG;
#pragma unroll
            for (int nt = 0; nt < 4; nt++) {
                int g0 = n0 + wn * 32 + nt * 8 + cq * 2;
                float2 v;
                v.x = d[mt][nt][half * 2 + 0] + biasb[g0];
                v.y = d[mt][nt][half * 2 + 1] + biasb[g0 + 1];
                *(float2*)(g_xg + base + g0) = v;
            }
        }
}

// ---------------- phase 2: 64 CTAs, all warps active, both cells resident ----------------
// CTA bx owns j-slice j0=bx*8 for BOTH cells. Warp w: rows perm[16w..16w+16), N=32 gate cols.
// A (h) fragments: direct LDG.128 from shuffled planes. W: smem uint2 (hi,lo). c: smem.
// smem: sW 2*32*261 uint2 (133632 B) + sc 512 float2 (4096 B) + perm 128 int (512 B)
#define SMEM2 (133632 + 4096 + 512)

__global__ __launch_bounds__(256, 1) void k_phase2(const float* __restrict__ Whh,
                                                   float* __restrict__ out) {
    extern __shared__ uint32_t smu[];
    uint2*  sW    = (uint2*)smu;                  // [2][32][261]
    float2* sc    = (float2*)(smu + 33408);       // [128][4]
    int*    permS = (int*)(smu + 33408 + 1024);   // 128

    const int tid = threadIdx.x, lane = tid & 31, w = tid >> 5;
    const int cq = lane & 3, rq = lane >> 2;
    const int bx = blockIdx.x;
    const int j0 = bx * 8;

    for (int idx = tid; idx < 2 * 32 * 256; idx += 256) {
        int cell = idx >> 13, rem = idx & 8191;
        int n = rem >> 8, kp = rem & 255;
        int grow = ((n >> 3) << 9) + j0 + (n & 7);
        float2 v = *(const float2*)(Whh + ((size_t)cell * GG + grow) * HH + kp * 2);
        uint32_t h, l; split2(v.x, v.y, h, l);
        sW[(cell * 32 + n) * 261 + kp] = make_uint2(h, l);
    }
    for (int idx = tid; idx < 512; idx += 256) sc[idx] = make_float2(0.f, 0.f);
    __syncthreads();

    for (int t = 0; t < SS; t++) {
        if (tid == 0) {
            unsigned r;
            do { asm volatile("ld.acquire.gpu.u32 %0, [%1];" : "=r"(r) : "l"(&g_release)); }
            while (r < (unsigned)t);
        }
        __syncthreads();
        if (tid < 128) permS[tid] = g_perm[t * 128 + tid];
        __syncthreads();

        const int cnt0 = __ldg(&g_cnt0[t]);
        const int r0 = w * 16 + rq, r1 = r0 + 8;
        const int b0 = permS[r0], b1 = permS[r1];
        const int cA = (w * 16 < cnt0) ? 0 : 1;
        const bool mixed = (cnt0 > w * 16) && (cnt0 < w * 16 + 16);
        const int rp = (t & 1) ^ 1, wp = t & 1;

        const uint4* p0h = (const uint4*)(g_hsh + (size_t)(rp * 128 + b0) * 256) + cq * 16;
        const uint4* p1h = (const uint4*)(g_hsh + (size_t)(rp * 128 + b1) * 256) + cq * 16;
        const uint4* p0l = (const uint4*)(g_hsl + (size_t)(rp * 128 + b0) * 256) + cq * 16;
        const uint4* p1l = (const uint4*)(g_hsl + (size_t)(rp * 128 + b1) * 256) + cq * 16;

        // prefetch gate pre-activations (DRAM) to hide under MMA
        const size_t xb0 = ((size_t)(t * 128 + b0)) * GG + j0 + cq * 2;
        const size_t xb1 = ((size_t)(t * 128 + b1)) * GG + j0 + cq * 2;
        float2 xp0[4], xp1[4];
#pragma unroll
        for (int g = 0; g < 4; g++) {
            xp0[g] = __ldcg((const float2*)(g_xg + xb0 + g * 512));
            xp1[g] = __ldcg((const float2*)(g_xg + xb1 + g * 512));
        }

        const uint2* wA = sW + cA * (32 * 261);
        const uint2* wB = sW + (32 * 261);     // cell 1 (second pass when mixed)

        float d[4][4], d2[4][4];
#pragma unroll
        for (int a = 0; a < 4; a++)
#pragma unroll
            for (int b = 0; b < 4; b++) { d[a][b] = 0.f; d2[a][b] = 0.f; }

        uint4 c0h = __ldcg(p0h), c1h = __ldcg(p1h);
        uint4 c0l = __ldcg(p0l), c1l = __ldcg(p1l);
#pragma unroll 4
        for (int ks = 0; ks < 16; ks++) {
            uint4 n0h, n1h, n0l, n1l;
            if (ks < 15) {
                n0h = __ldcg(p0h + ks + 1); n1h = __ldcg(p1h + ks + 1);
                n0l = __ldcg(p0l + ks + 1); n1l = __ldcg(p1l + ks + 1);
            }
#pragma unroll
            for (int kc = 0; kc < 2; kc++) {
                uint32_t ah0 = kc ? c0h.z : c0h.x, ah1 = kc ? c1h.z : c1h.x;
                uint32_t ah2 = kc ? c0h.w : c0h.y, ah3 = kc ? c1h.w : c1h.y;
                uint32_t al0 = kc ? c0l.z : c0l.x, al1 = kc ? c1l.z : c1l.x;
                uint32_t al2 = kc ? c0l.w : c0l.y, al3 = kc ? c1l.w : c1l.y;
                const int kg = ks * 16 + kc * 8 + cq;
#pragma unroll
                for (int nt = 0; nt < 4; nt++) {
                    const int n = nt * 8 + rq;
                    uint2 w0 = wA[n * 261 + kg], w1 = wA[n * 261 + kg + 4];
                    mma16(d[nt], ah0, ah1, ah2, ah3, w0.x, w1.x);
                    mma16(d[nt], ah0, ah1, ah2, ah3, w0.y, w1.y);
                    mma16(d[nt], al0, al1, al2, al3, w0.x, w1.x);
                }
                if (mixed) {
#pragma unroll
                    for (int nt = 0; nt < 4; nt++) {
                        const int n = nt * 8 + rq;
                        uint2 w0 = wB[n * 261 + kg], w1 = wB[n * 261 + kg + 4];
                        mma16(d2[nt], ah0, ah1, ah2, ah3, w0.x, w1.x);
                        mma16(d2[nt], ah0, ah1, ah2, ah3, w0.y, w1.y);
                        mma16(d2[nt], al0, al1, al2, al3, w0.x, w1.x);
                    }
                }
            }
            c0h = n0h; c1h = n1h; c0l = n0l; c1l = n1l;
        }

        // epilogue (row r0 -> half 0, row r1 -> half 1)
#pragma unroll
        for (int half = 0; half < 2; half++) {
            const int rm = half ? r1 : r0;
            const int b  = half ? b1 : b0;
            const float2* xp = half ? xp1 : xp0;
            const int  cr   = (rm < cnt0) ? 0 : 1;
            const bool useA = (cr == cA);
            float vi0 = useA ? d[0][half*2]   : d2[0][half*2];
            float vi1 = useA ? d[0][half*2+1] : d2[0][half*2+1];
            float vf0 = useA ? d[1][half*2]   : d2[1][half*2];
            float vf1 = useA ? d[1][half*2+1] : d2[1][half*2+1];
            float vg0 = useA ? d[2][half*2]   : d2[2][half*2];
            float vg1 = useA ? d[2][half*2+1] : d2[2][half*2+1];
            float vo0 = useA ? d[3][half*2]   : d2[3][half*2];
            float vo1 = useA ? d[3][half*2+1] : d2[3][half*2+1];
            float2 cc = sc[b * 4 + cq];
            float i0 = sigm(xp[0].x + vi0), i1 = sigm(xp[0].y + vi1);
            float f0 = sigm(xp[1].x + vf0), f1 = sigm(xp[1].y + vf1);
            float gg0 = tanhf(xp[2].x + vg0), gg1 = tanhf(xp[2].y + vg1);
            float o0 = sigm(xp[3].x + vo0), o1 = sigm(xp[3].y + vo1);
            float c0 = f0 * cc.x + i0 * gg0;
            float c1 = f1 * cc.y + i1 * gg1;
            float h0 = o0 * tanhf(c0);
            float h1 = o1 * tanhf(c1);
            sc[b * 4 + cq] = make_float2(c0, c1);
            uint32_t hh, hl; split2(h0, h1, hh, hl);
            g_hsh[(size_t)(wp * 128 + b) * 256 + cq * 64 + bx] = hh;
            g_hsl[(size_t)(wp * 128 + b) * 256 + cq * 64 + bx] = hl;
            *(float2*)(out + (size_t)b * (SS * HH) + t * HH + j0 + cq * 2) = make_float2(h0, h1);
        }

        __threadfence();
        __syncthreads();
        if (tid == 0) {
            unsigned v = atomicAdd(&g_count, 1u) + 1u;
            if (v == 64u * (unsigned)(t + 1)) {
                asm volatile("st.release.gpu.u32 [%0], %1;" :: "l"(&g_release), "r"((unsigned)(t + 1)));
            }
        }
    }

    // write c back to global for k_tail
    __syncthreads();
    for (int idx = tid; idx < 512; idx += 256) {
        int b = idx >> 2, q = idx & 3;
        *(float2*)(g_c + b * HH + j0 + q * 2) = sc[idx];
    }
}

__global__ void k_tail(float* __restrict__ out) {
    int i = blockIdx.x * 256 + threadIdx.x;
    if (i < BB * HH) {
        int b = i >> 9, j = i & 511;
        int p = j >> 1;
        int addr = (128 + b) * 256 + (p & 3) * 64 + (p >> 2);   // buf 1 (t=1023)
        uint32_t vh = g_hsh[addr], vl = g_hsl[addr];
        float h = (j & 1) ? (bf_hi(vh) + bf_hi(vl)) : (bf_lo(vh) + bf_lo(vl));
        out[(size_t)BSH + i] = h;
        out[(size_t)BSH + BB * HH + i] = g_c[i];
    }
}

extern "C" void kernel_launch(void* const* d_in, const int* in_sizes, int n_in,
                              void* d_out, int out_size) {
    const int*   inp   = (const int*)d_in[0];
    const float* embed = (const float*)d_in[1];
    const float* Wih   = (const float*)d_in[2];
    const float* Whh   = (const float*)d_in[3];
    const float* bih   = (const float*)d_in[4];
    const float* bhh   = (const float*)d_in[5];
    float* out = (float*)d_out;

    cudaFuncSetAttribute(k_phase1, cudaFuncAttributeMaxDynamicSharedMemorySize, SMEM1);
    cudaFuncSetAttribute(k_phase2, cudaFuncAttributeMaxDynamicSharedMemorySize, SMEM2);

    k_init<<<2120, 256>>>(bih, bhh, embed, Wih);
    k_setup<<<1, 1024>>>(inp);
    k_phase1<<<dim3(32, 1025), 256, SMEM1>>>();
    k_phase2<<<64, 256, SMEM2>>>(Whh, out);
    if (out_size >= BSH + 2 * BB * HH) k_tail<<<256, 256>>>(out);
}

// round 16
// speedup vs baseline: 1.4199x; 1.4199x over previous
#include <cuda_runtime.h>
#include <cuda_bf16.h>
#include <cstdint>

#define BB 128
#define SS 1024
#define EE 512
#define HH 512
#define GG 2048
#define BSH (128*1024*512)

// ---------------- device scratch ----------------
__device__ float    g_xg[(size_t)SS * BB * GG];   // 1 GiB Xg[t][b][g]
__device__ float    g_h[2 * BB * HH];             // double buffered
__device__ float    g_c[BB * HH];
__device__ float    g_biasc[2 * GG];
__device__ int      g_perm[SS * BB];
__device__ int      g_cnt0[SS];
__device__ int      g_flat[1025 * 128];
__device__ int      g_total0_pad;
__device__ unsigned g_count;
__device__ unsigned g_release;

// ---------------- helpers ----------------
__device__ __forceinline__ void split2(float x, float y, uint32_t& h, uint32_t& l) {
    unsigned short hx = __bfloat16_as_ushort(__float2bfloat16(x));
    unsigned short hy = __bfloat16_as_ushort(__float2bfloat16(y));
    float fx = __bfloat162float(__ushort_as_bfloat16(hx));
    float fy = __bfloat162float(__ushort_as_bfloat16(hy));
    unsigned short lx = __bfloat16_as_ushort(__float2bfloat16(x - fx));
    unsigned short ly = __bfloat16_as_ushort(__float2bfloat16(y - fy));
    h = ((uint32_t)hy << 16) | hx;
    l = ((uint32_t)ly << 16) | lx;
}

__device__ __forceinline__ void mma16(float* d, uint32_t a0, uint32_t a1, uint32_t a2,
                                      uint32_t a3, uint32_t b0, uint32_t b1) {
    asm volatile(
        "mma.sync.aligned.m16n8k16.row.col.f32.bf16.bf16.f32 "
        "{%0,%1,%2,%3},{%4,%5,%6,%7},{%8,%9},{%0,%1,%2,%3};\n"
        : "+f"(d[0]), "+f"(d[1]), "+f"(d[2]), "+f"(d[3])
        : "r"(a0), "r"(a1), "r"(a2), "r"(a3), "r"(b0), "r"(b1));
}

__device__ __forceinline__ float sigm(float x) {
    return __fdividef(1.f, 1.f + __expf(-x));
}

// ---------------- k_init ----------------
__global__ void k_init(const float* __restrict__ bih, const float* __restrict__ bhh) {
    int i = blockIdx.x * 256 + threadIdx.x;
    if (i < 2 * GG) g_biasc[i] = bih[i] + bhh[i];
    if (i < BB * HH) { g_c[i] = 0.f; g_h[i] = 0.f; g_h[BB * HH + i] = 0.f; }
    if (i == 0) { g_count = 0u; g_release = 0u; }
}

// ---------------- k_setup: perm + scan + flat fused (1 block x 1024) ----------------
__global__ void k_setup(const int* __restrict__ inp) {
    __shared__ int s[1024];
    int t = threadIdx.x;
    int i0 = 0, i1 = 128;
    for (int b = 0; b < 128; b++) {
        int v = inp[b * SS + t] & 1;
        if (!v) g_perm[t * 128 + i0++] = b;
        else    g_perm[t * 128 + --i1] = b;
    }
    g_cnt0[t] = i0;
    s[t] = i0;
    __syncthreads();
    for (int off = 1; off < 1024; off <<= 1) {
        int v = (t >= off) ? s[t - off] : 0;
        __syncthreads();
        s[t] += v;
        __syncthreads();
    }
    int tot0 = s[1023];
    int t0p = (tot0 + 127) & ~127;
    int base0 = s[t] - i0;
    int base1 = t0p + 128 * t - base0;
    for (int i = 0; i < i0; i++)
        g_flat[base0 + i] = (g_perm[t * 128 + i] << 10) | t;
    for (int i = i0; i < 128; i++)
        g_flat[base1 + (i - i0)] = (g_perm[t * 128 + i] << 10) | t;
    if (t == 0) g_total0_pad = t0p;
    int mid = t0p - tot0;
    if (t < mid) g_flat[tot0 + t] = -1;
    int fe = t0p + (SS * BB - tot0);
    int tail = 1025 * 128 - fe;
    if (t < tail) g_flat[fe + t] = -1;
}

// ---------------- phase 1: Xg = W_ih[cell] x + bias  (bf16x3 gather-GEMM, R10 form) ----------------
#define SMEM1 ((5120 + 5120 + 2560 + 2560 + 128) * 4)

__global__ __launch_bounds__(256) void k_phase1(const float* __restrict__ embed,
                                                const float* __restrict__ Wih) {
    extern __shared__ uint32_t smu[];
    uint32_t* sAh = smu;
    uint32_t* sAl = sAh + 5120;
    uint32_t* sBh = sAl + 5120;
    uint32_t* sBl = sBh + 2560;
    int*      toks = (int*)(sBl + 2560);

    const int tid = threadIdx.x, lane = tid & 31, warp = tid >> 5;
    const int wm = warp & 3, wn = warp >> 2;
    const int m0 = blockIdx.y * 128, n0 = blockIdx.x * 64;

    if (tid < 128) toks[tid] = g_flat[m0 + tid];
    __syncthreads();
    const int cell = (m0 >= g_total0_pad) ? 1 : 0;
    const float* Wb = Wih + (size_t)cell * GG * EE;
    const float* biasb = g_biasc + cell * GG;

    const int ar = tid >> 1, asg = tid & 1;
    const int bn = tid >> 2, bq = tid & 3;
    const int atok = toks[ar];

    float4 va[4], vb[2];
    if (atok >= 0) {
        const float4* p = (const float4*)(embed + (size_t)atok * EE + asg * 16);
        va[0] = __ldg(p); va[1] = __ldg(p + 1); va[2] = __ldg(p + 2); va[3] = __ldg(p + 3);
    } else va[0] = va[1] = va[2] = va[3] = make_float4(0, 0, 0, 0);
    {
        const float4* q = (const float4*)(Wb + (size_t)(n0 + bn) * EE + bq * 8);
        vb[0] = __ldg(q); vb[1] = __ldg(q + 1);
    }

    float d[2][4][4];
#pragma unroll
    for (int a = 0; a < 2; a++)
#pragma unroll
        for (int b = 0; b < 4; b++)
#pragma unroll
            for (int c = 0; c < 4; c++) d[a][b][c] = 0.f;

    const int cq = lane & 3, rq = lane >> 2;

    for (int ks = 0; ks < 16; ks++) {
        int buf = ks & 1;
        {
            uint32_t h0, l0, h1, l1;
#pragma unroll
            for (int i = 0; i < 4; i++) {
                split2(va[i].x, va[i].y, h0, l0);
                split2(va[i].z, va[i].w, h1, l1);
                int ai = buf * 2560 + ar * 20 + asg * 8 + i * 2;
                sAh[ai] = h0; sAh[ai + 1] = h1;
                sAl[ai] = l0; sAl[ai + 1] = l1;
            }
#pragma unroll
            for (int i = 0; i < 2; i++) {
                split2(vb[i].x, vb[i].y, h0, l0);
                split2(vb[i].z, vb[i].w, h1, l1);
                int bi = buf * 1280 + bn * 20 + bq * 4 + i * 2;
                sBh[bi] = h0; sBh[bi + 1] = h1;
                sBl[bi] = l0; sBl[bi + 1] = l1;
            }
        }
        __syncthreads();
        if (ks < 15) {
            int k0 = (ks + 1) * 32;
            if (atok >= 0) {
                const float4* p = (const float4*)(embed + (size_t)atok * EE + k0 + asg * 16);
                va[0] = __ldg(p); va[1] = __ldg(p + 1); va[2] = __ldg(p + 2); va[3] = __ldg(p + 3);
            }
            const float4* q = (const float4*)(Wb + (size_t)(n0 + bn) * EE + k0 + bq * 8);
            vb[0] = __ldg(q); vb[1] = __ldg(q + 1);
        }
        const uint32_t* Ah = sAh + buf * 2560;
        const uint32_t* Al = sAl + buf * 2560;
        const uint32_t* Bh = sBh + buf * 1280;
        const uint32_t* Bl = sBl + buf * 1280;
#pragma unroll
        for (int kc = 0; kc < 2; kc++) {
            int kb = kc * 8 + cq;
            uint32_t bh[4][2], bl[4][2];
#pragma unroll
            for (int nt = 0; nt < 4; nt++) {
                int n = wn * 32 + nt * 8 + rq;
                bh[nt][0] = Bh[n * 20 + kb]; bh[nt][1] = Bh[n * 20 + kb + 4];
                bl[nt][0] = Bl[n * 20 + kb]; bl[nt][1] = Bl[n * 20 + kb + 4];
            }
#pragma unroll
            for (int mt = 0; mt < 2; mt++) {
                int r = wm * 32 + mt * 16 + rq;
                uint32_t ah0 = Ah[r * 20 + kb],     ah1 = Ah[(r + 8) * 20 + kb];
                uint32_t ah2 = Ah[r * 20 + kb + 4], ah3 = Ah[(r + 8) * 20 + kb + 4];
                uint32_t al0 = Al[r * 20 + kb],     al1 = Al[(r + 8) * 20 + kb];
                uint32_t al2 = Al[r * 20 + kb + 4], al3 = Al[(r + 8) * 20 + kb + 4];
#pragma unroll
                for (int nt = 0; nt < 4; nt++) {
                    mma16(d[mt][nt], ah0, ah1, ah2, ah3, bh[nt][0], bh[nt][1]);
                    mma16(d[mt][nt], ah0, ah1, ah2, ah3, bl[nt][0], bl[nt][1]);
                    mma16(d[mt][nt], al0, al1, al2, al3, bh[nt][0], bh[nt][1]);
                }
            }
        }
    }

#pragma unroll
    for (int mt = 0; mt < 2; mt++)
#pragma unroll
        for (int half = 0; half < 2; half++) {
            int r = wm * 32 + mt * 16 + rq + half * 8;
            int tok = toks[r];
            if (tok < 0) continue;
            int tt = tok & 1023, b = tok >> 10;
            size_t base = ((size_t)(tt * 128 + b)) * GG;
#pragma unroll
            for (int nt = 0; nt < 4; nt++) {
                int g0 = n0 + wn * 32 + nt * 8 + cq * 2;
                float2 v;
                v.x = d[mt][nt][half * 2 + 0] + biasb[g0];
                v.y = d[mt][nt][half * 2 + 1] + biasb[g0 + 1];
                *(float2*)(g_xg + base + g0) = v;
            }
        }
}

// ---------------- phase 2: persistent recurrence (R10 structure, K64 stages, xg prefetch) ----------------
// 128 CTAs: cell = bx>>6, j0 = (bx&63)*8. N=32 gate cols ({i,f,g,o} x 8), K=512 in 8 stages of 64.
// u32: sWh 32*260=8320, sWl 8320, sAh 2*128*36=9216, sAl 9216, perm 128
#define SMEM2 ((2*8320 + 2*9216 + 128) * 4)

__global__ __launch_bounds__(256, 1) void k_phase2(const float* __restrict__ Whh,
                                                   float* __restrict__ out) {
    extern __shared__ uint32_t smu[];
    uint32_t* sWh = smu;                 // 32 x 260 (packed bf16 pairs along K)
    uint32_t* sWl = sWh + 8320;
    uint32_t* sAh = sWl + 8320;          // 2 x 128 x 36 (32 pairs + 4 pad)
    uint32_t* sAl = sAh + 9216;
    int*      permS = (int*)(sAl + 9216);

    const int tid = threadIdx.x, lane = tid & 31, w = tid >> 5;
    const int cq = lane & 3, rq = lane >> 2;
    const int cell = blockIdx.x >> 6;
    const int j0 = (blockIdx.x & 63) * 8;

    for (int idx = tid; idx < 32 * 256; idx += 256) {
        int n = idx >> 8, kp = idx & 255;
        int grow = ((n >> 3) << 9) + j0 + (n & 7);
        float2 v = *(const float2*)(Whh + ((size_t)cell * GG + grow) * HH + kp * 2);
        uint32_t h, l; split2(v.x, v.y, h, l);
        sWh[n * 260 + kp] = h;
        sWl[n * 260 + kp] = l;
    }
    __syncthreads();

    const int ar = tid >> 1, asg = tid & 1;   // loader: 2 threads/row, 32 floats each

    for (int t = 0; t < SS; t++) {
        if (tid == 0) {
            unsigned r;
            do { asm volatile("ld.acquire.gpu.u32 %0, [%1];" : "=r"(r) : "l"(&g_release)); }
            while (r < (unsigned)t);
        }
        __syncthreads();

        int cnt0 = g_cnt0[t];
        int Mc = cell ? (128 - cnt0) : cnt0;
        int base = cell ? cnt0 : 0;
        if (tid < 128) permS[tid] = (tid < Mc) ? g_perm[t * 128 + base + tid] : 0;
        __syncthreads();
        const int Mpad = (Mc + 15) & ~15;
        const int rp = (t & 1) ^ 1;
        const bool act = (w * 16) < Mc;
        const bool ald = ar < Mpad;
        const int ab = permS[ar];
        const float* hbase = g_h + (size_t)rp * (BB * HH) + (size_t)ab * HH;

        // prefetch gate pre-activations (DRAM) so they land under the MMA loop
        float2 xp[2][4];
        int bb[2];
        if (act) {
#pragma unroll
            for (int half = 0; half < 2; half++) {
                int rm = w * 16 + rq + half * 8;
                bb[half] = permS[(rm < Mc) ? rm : 0];
                size_t xb = ((size_t)(t * 128 + bb[half])) * GG + j0 + cq * 2;
#pragma unroll
                for (int g = 0; g < 4; g++)
                    xp[half][g] = __ldcg((const float2*)(g_xg + xb + g * 512));
            }
        }

        float d[4][4];
#pragma unroll
        for (int a = 0; a < 4; a++)
#pragma unroll
            for (int b = 0; b < 4; b++) d[a][b] = 0.f;

        float4 va[8];
        if (ald) {
            const float4* p = (const float4*)hbase + asg * 8;
#pragma unroll
            for (int i = 0; i < 8; i++) va[i] = __ldcg(p + i);
        }
        for (int ks = 0; ks < 8; ks++) {
            const int buf = ks & 1;
            if (ald) {
                uint32_t h0, l0, h1, l1;
#pragma unroll
                for (int i = 0; i < 8; i++) {
                    split2(va[i].x, va[i].y, h0, l0);
                    split2(va[i].z, va[i].w, h1, l1);
                    int ai = buf * 4608 + ar * 36 + asg * 16 + i * 2;
                    sAh[ai] = h0; sAh[ai + 1] = h1;
                    sAl[ai] = l0; sAl[ai + 1] = l1;
                }
            }
            __syncthreads();
            if (ks < 7 && ald) {
                const float4* p = (const float4*)(hbase + (ks + 1) * 64) + asg * 8;
#pragma unroll
                for (int i = 0; i < 8; i++) va[i] = __ldcg(p + i);
            }
            if (act) {
                const uint32_t* Ah = sAh + buf * 4608;
                const uint32_t* Al = sAl + buf * 4608;
                const int r0w = w * 16 + rq;
#pragma unroll
                for (int kc = 0; kc < 4; kc++) {
                    const int kb = kc * 8 + cq;
                    const int kg = ks * 32 + kb;
                    uint32_t ah0 = Ah[r0w * 36 + kb],     ah1 = Ah[(r0w + 8) * 36 + kb];
                    uint32_t ah2 = Ah[r0w * 36 + kb + 4], ah3 = Ah[(r0w + 8) * 36 + kb + 4];
                    uint32_t al0 = Al[r0w * 36 + kb],     al1 = Al[(r0w + 8) * 36 + kb];
                    uint32_t al2 = Al[r0w * 36 + kb + 4], al3 = Al[(r0w + 8) * 36 + kb + 4];
#pragma unroll
                    for (int nt = 0; nt < 4; nt++) {
                        const int n = nt * 8 + rq;
                        uint32_t bh0 = sWh[n * 260 + kg], bh1 = sWh[n * 260 + kg + 4];
                        uint32_t bl0 = sWl[n * 260 + kg], bl1 = sWl[n * 260 + kg + 4];
                        mma16(d[nt], ah0, ah1, ah2, ah3, bh0, bh1);
                        mma16(d[nt], ah0, ah1, ah2, ah3, bl0, bl1);
                        mma16(d[nt], al0, al1, al2, al3, bh0, bh1);
                    }
                }
            }
        }

        if (act) {
            const int wp = t & 1;
#pragma unroll
            for (int half = 0; half < 2; half++) {
                int rm = w * 16 + rq + half * 8;
                if (rm < Mc) {
                    int b = bb[half];
                    int jj = j0 + cq * 2;
                    float2 cc = __ldcg((const float2*)(g_c + b * HH + jj));
                    float i0 = sigm(xp[half][0].x + d[0][half * 2]);
                    float i1 = sigm(xp[half][0].y + d[0][half * 2 + 1]);
                    float f0 = sigm(xp[half][1].x + d[1][half * 2]);
                    float f1 = sigm(xp[half][1].y + d[1][half * 2 + 1]);
                    float gg0 = tanhf(xp[half][2].x + d[2][half * 2]);
                    float gg1 = tanhf(xp[half][2].y + d[2][half * 2 + 1]);
                    float o0 = sigm(xp[half][3].x + d[3][half * 2]);
                    float o1 = sigm(xp[half][3].y + d[3][half * 2 + 1]);
                    float c0 = f0 * cc.x + i0 * gg0;
                    float c1 = f1 * cc.y + i1 * gg1;
                    float h0 = o0 * tanhf(c0);
                    float h1 = o1 * tanhf(c1);
                    *(float2*)(g_c + b * HH + jj) = make_float2(c0, c1);
                    *(float2*)(g_h + (size_t)wp * (BB * HH) + b * HH + jj) = make_float2(h0, h1);
                    *(float2*)(out + (size_t)b * (SS * HH) + t * HH + jj) = make_float2(h0, h1);
                }
            }
        }
        __threadfence();
        __syncthreads();
        if (tid == 0) {
            unsigned v = atomicAdd(&g_count, 1u) + 1u;
            if (v == 128u * (unsigned)(t + 1)) {
                asm volatile("st.release.gpu.u32 [%0], %1;" :: "l"(&g_release), "r"((unsigned)(t + 1)));
            }
        }
    }
}

__global__ void k_tail(float* __restrict__ out) {
    int i = blockIdx.x * 256 + threadIdx.x;
    if (i < BB * HH) {
        out[(size_t)BSH + i] = g_h[BB * HH + i];            // h_last (t=1023, parity 1)
        out[(size_t)BSH + BB * HH + i] = g_c[i];            // c_last
    }
}

extern "C" void kernel_launch(void* const* d_in, const int* in_sizes, int n_in,
                              void* d_out, int out_size) {
    const int*   inp   = (const int*)d_in[0];
    const float* embed = (const float*)d_in[1];
    const float* Wih   = (const float*)d_in[2];
    const float* Whh   = (const float*)d_in[3];
    const float* bih   = (const float*)d_in[4];
    const float* bhh   = (const float*)d_in[5];
    float* out = (float*)d_out;

    cudaFuncSetAttribute(k_phase1, cudaFuncAttributeMaxDynamicSharedMemorySize, SMEM1);
    cudaFuncSetAttribute(k_phase2, cudaFuncAttributeMaxDynamicSharedMemorySize, SMEM2);

    k_init<<<512, 256>>>(bih, bhh);
    k_setup<<<1, 1024>>>(inp);
    k_phase1<<<dim3(32, 1025), 256, SMEM1>>>(embed, Wih);
    k_phase2<<<128, 256, SMEM2>>>(Whh, out);
    if (out_size >= BSH + 2 * BB * HH) k_tail<<<256, 256>>>(out);
}

// round 17
// speedup vs baseline: 1.4964x; 1.0539x over previous
#include <cuda_runtime.h>
#include <cuda_bf16.h>
#include <cstdint>

#define BB 128
#define SS 1024
#define EE 512
#define HH 512
#define GG 2048
#define BSH (128*1024*512)

// ---------------- device scratch ----------------
__device__ float    g_xg[(size_t)SS * BB * GG];   // 1 GiB Xg[t][b][g]
__device__ float    g_h[2 * BB * HH];             // double buffered
__device__ float    g_c[BB * HH];
__device__ float    g_biasc[2 * GG];
__device__ int      g_perm[SS * BB];
__device__ int      g_cnt0[SS];
__device__ int      g_flat[1025 * 128];
__device__ int      g_total0_pad;
__device__ unsigned g_count;
__device__ unsigned g_release;

// ---------------- helpers ----------------
__device__ __forceinline__ void split2(float x, float y, uint32_t& h, uint32_t& l) {
    unsigned short hx = __bfloat16_as_ushort(__float2bfloat16(x));
    unsigned short hy = __bfloat16_as_ushort(__float2bfloat16(y));
    float fx = __bfloat162float(__ushort_as_bfloat16(hx));
    float fy = __bfloat162float(__ushort_as_bfloat16(hy));
    unsigned short lx = __bfloat16_as_ushort(__float2bfloat16(x - fx));
    unsigned short ly = __bfloat16_as_ushort(__float2bfloat16(y - fy));
    h = ((uint32_t)hy << 16) | hx;
    l = ((uint32_t)ly << 16) | lx;
}

__device__ __forceinline__ void mma16(float* d, uint32_t a0, uint32_t a1, uint32_t a2,
                                      uint32_t a3, uint32_t b0, uint32_t b1) {
    asm volatile(
        "mma.sync.aligned.m16n8k16.row.col.f32.bf16.bf16.f32 "
        "{%0,%1,%2,%3},{%4,%5,%6,%7},{%8,%9},{%0,%1,%2,%3};\n"
        : "+f"(d[0]), "+f"(d[1]), "+f"(d[2]), "+f"(d[3])
        : "r"(a0), "r"(a1), "r"(a2), "r"(a3), "r"(b0), "r"(b1));
}

__device__ __forceinline__ float sigm(float x) {
    return __fdividef(1.f, 1.f + __expf(-x));
}

// branch-free fast tanh: 2 MUFU, ~7 inst, rel err ~1e-7 — replaces library tanhf
__device__ __forceinline__ float tanh_fast(float x) {
    float e = __expf(-2.f * fabsf(x));
    float r = __fdividef(1.f - e, 1.f + e);
    return copysignf(r, x);
}

// ---------------- k_init ----------------
__global__ void k_init(const float* __restrict__ bih, const float* __restrict__ bhh) {
    int i = blockIdx.x * 256 + threadIdx.x;
    if (i < 2 * GG) g_biasc[i] = bih[i] + bhh[i];
    if (i < BB * HH) { g_c[i] = 0.f; g_h[i] = 0.f; g_h[BB * HH + i] = 0.f; }
    if (i == 0) { g_count = 0u; g_release = 0u; }
}

// ---------------- k_setup: perm + scan + flat fused (1 block x 1024) ----------------
__global__ void k_setup(const int* __restrict__ inp) {
    __shared__ int s[1024];
    int t = threadIdx.x;
    int i0 = 0, i1 = 128;
    for (int b = 0; b < 128; b++) {
        int v = inp[b * SS + t] & 1;
        if (!v) g_perm[t * 128 + i0++] = b;
        else    g_perm[t * 128 + --i1] = b;
    }
    g_cnt0[t] = i0;
    s[t] = i0;
    __syncthreads();
    for (int off = 1; off < 1024; off <<= 1) {
        int v = (t >= off) ? s[t - off] : 0;
        __syncthreads();
        s[t] += v;
        __syncthreads();
    }
    int tot0 = s[1023];
    int t0p = (tot0 + 127) & ~127;
    int base0 = s[t] - i0;
    int base1 = t0p + 128 * t - base0;
    for (int i = 0; i < i0; i++)
        g_flat[base0 + i] = (g_perm[t * 128 + i] << 10) | t;
    for (int i = i0; i < 128; i++)
        g_flat[base1 + (i - i0)] = (g_perm[t * 128 + i] << 10) | t;
    if (t == 0) g_total0_pad = t0p;
    int mid = t0p - tot0;
    if (t < mid) g_flat[tot0 + t] = -1;
    int fe = t0p + (SS * BB - tot0);
    int tail = 1025 * 128 - fe;
    if (t < tail) g_flat[fe + t] = -1;
}

// ---------------- phase 1: Xg = W_ih[cell] x + bias  (bf16x3 gather-GEMM, R10 form) ----------------
#define SMEM1 ((5120 + 5120 + 2560 + 2560 + 128) * 4)

__global__ __launch_bounds__(256) void k_phase1(const float* __restrict__ embed,
                                                const float* __restrict__ Wih) {
    extern __shared__ uint32_t smu[];
    uint32_t* sAh = smu;
    uint32_t* sAl = sAh + 5120;
    uint32_t* sBh = sAl + 5120;
    uint32_t* sBl = sBh + 2560;
    int*      toks = (int*)(sBl + 2560);

    const int tid = threadIdx.x, lane = tid & 31, warp = tid >> 5;
    const int wm = warp & 3, wn = warp >> 2;
    const int m0 = blockIdx.y * 128, n0 = blockIdx.x * 64;

    if (tid < 128) toks[tid] = g_flat[m0 + tid];
    __syncthreads();
    const int cell = (m0 >= g_total0_pad) ? 1 : 0;
    const float* Wb = Wih + (size_t)cell * GG * EE;
    const float* biasb = g_biasc + cell * GG;

    const int ar = tid >> 1, asg = tid & 1;
    const int bn = tid >> 2, bq = tid & 3;
    const int atok = toks[ar];

    float4 va[4], vb[2];
    if (atok >= 0) {
        const float4* p = (const float4*)(embed + (size_t)atok * EE + asg * 16);
        va[0] = __ldg(p); va[1] = __ldg(p + 1); va[2] = __ldg(p + 2); va[3] = __ldg(p + 3);
    } else va[0] = va[1] = va[2] = va[3] = make_float4(0, 0, 0, 0);
    {
        const float4* q = (const float4*)(Wb + (size_t)(n0 + bn) * EE + bq * 8);
        vb[0] = __ldg(q); vb[1] = __ldg(q + 1);
    }

    float d[2][4][4];
#pragma unroll
    for (int a = 0; a < 2; a++)
#pragma unroll
        for (int b = 0; b < 4; b++)
#pragma unroll
            for (int c = 0; c < 4; c++) d[a][b][c] = 0.f;

    const int cq = lane & 3, rq = lane >> 2;

    for (int ks = 0; ks < 16; ks++) {
        int buf = ks & 1;
        {
            uint32_t h0, l0, h1, l1;
#pragma unroll
            for (int i = 0; i < 4; i++) {
                split2(va[i].x, va[i].y, h0, l0);
                split2(va[i].z, va[i].w, h1, l1);
                int ai = buf * 2560 + ar * 20 + asg * 8 + i * 2;
                sAh[ai] = h0; sAh[ai + 1] = h1;
                sAl[ai] = l0; sAl[ai + 1] = l1;
            }
#pragma unroll
            for (int i = 0; i < 2; i++) {
                split2(vb[i].x, vb[i].y, h0, l0);
                split2(vb[i].z, vb[i].w, h1, l1);
                int bi = buf * 1280 + bn * 20 + bq * 4 + i * 2;
                sBh[bi] = h0; sBh[bi + 1] = h1;
                sBl[bi] = l0; sBl[bi + 1] = l1;
            }
        }
        __syncthreads();
        if (ks < 15) {
            int k0 = (ks + 1) * 32;
            if (atok >= 0) {
                const float4* p = (const float4*)(embed + (size_t)atok * EE + k0 + asg * 16);
                va[0] = __ldg(p); va[1] = __ldg(p + 1); va[2] = __ldg(p + 2); va[3] = __ldg(p + 3);
            }
            const float4* q = (const float4*)(Wb + (size_t)(n0 + bn) * EE + k0 + bq * 8);
            vb[0] = __ldg(q); vb[1] = __ldg(q + 1);
        }
        const uint32_t* Ah = sAh + buf * 2560;
        const uint32_t* Al = sAl + buf * 2560;
        const uint32_t* Bh = sBh + buf * 1280;
        const uint32_t* Bl = sBl + buf * 1280;
#pragma unroll
        for (int kc = 0; kc < 2; kc++) {
            int kb = kc * 8 + cq;
            uint32_t bh[4][2], bl[4][2];
#pragma unroll
            for (int nt = 0; nt < 4; nt++) {
                int n = wn * 32 + nt * 8 + rq;
                bh[nt][0] = Bh[n * 20 + kb]; bh[nt][1] = Bh[n * 20 + kb + 4];
                bl[nt][0] = Bl[n * 20 + kb]; bl[nt][1] = Bl[n * 20 + kb + 4];
            }
#pragma unroll
            for (int mt = 0; mt < 2; mt++) {
                int r = wm * 32 + mt * 16 + rq;
                uint32_t ah0 = Ah[r * 20 + kb],     ah1 = Ah[(r + 8) * 20 + kb];
                uint32_t ah2 = Ah[r * 20 + kb + 4], ah3 = Ah[(r + 8) * 20 + kb + 4];
                uint32_t al0 = Al[r * 20 + kb],     al1 = Al[(r + 8) * 20 + kb];
                uint32_t al2 = Al[r * 20 + kb + 4], al3 = Al[(r + 8) * 20 + kb + 4];
#pragma unroll
                for (int nt = 0; nt < 4; nt++) {
                    mma16(d[mt][nt], ah0, ah1, ah2, ah3, bh[nt][0], bh[nt][1]);
                    mma16(d[mt][nt], ah0, ah1, ah2, ah3, bl[nt][0], bl[nt][1]);
                    mma16(d[mt][nt], al0, al1, al2, al3, bh[nt][0], bh[nt][1]);
                }
            }
        }
    }

#pragma unroll
    for (int mt = 0; mt < 2; mt++)
#pragma unroll
        for (int half = 0; half < 2; half++) {
            int r = wm * 32 + mt * 16 + rq + half * 8;
            int tok = toks[r];
            if (tok < 0) continue;
            int tt = tok & 1023, b = tok >> 10;
            size_t base = ((size_t)(tt * 128 + b)) * GG;
#pragma unroll
            for (int nt = 0; nt < 4; nt++) {
                int g0 = n0 + wn * 32 + nt * 8 + cq * 2;
                float2 v;
                v.x = d[mt][nt][half * 2 + 0] + biasb[g0];
                v.y = d[mt][nt][half * 2 + 1] + biasb[g0 + 1];
                *(float2*)(g_xg + base + g0) = v;
            }
        }
}

// ---------------- phase 2: persistent recurrence (exact R10 structure, fast tanh) ----------------
// 128 CTAs: cell = bx>>6, j0 = (bx&63)*8. N = 32 gate cols ({i,f,g,o} x 8). K = 512 in 16 stages.
// u32: sWh 32*260=8320, sWl 8320, sAh 2*128*20=5120, sAl 5120, perm 128
#define SMEM2 ((8320 + 8320 + 5120 + 5120 + 128) * 4)

__global__ __launch_bounds__(256, 1) void k_phase2(const float* __restrict__ Whh,
                                                   float* __restrict__ out) {
    extern __shared__ uint32_t smu[];
    uint32_t* sWh = smu;                 // 32 x 260
    uint32_t* sWl = sWh + 8320;
    uint32_t* sAh = sWl + 8320;          // 2 x 128 x 20
    uint32_t* sAl = sAh + 5120;
    int*      permS = (int*)(sAl + 5120);

    const int tid = threadIdx.x, lane = tid & 31, w = tid >> 5;
    const int cell = blockIdx.x >> 6;
    const int j0 = (blockIdx.x & 63) * 8;

    // W_hh slice -> resident smem, bf16 hi/lo split, packed pairs along K
    for (int idx = tid; idx < 32 * 256; idx += 256) {
        int n = idx >> 8, kp = idx & 255;
        int grow = ((n >> 3) << 9) + j0 + (n & 7);
        float2 v = *(const float2*)(Whh + ((size_t)cell * GG + grow) * HH + kp * 2);
        uint32_t h, l; split2(v.x, v.y, h, l);
        sWh[n * 260 + kp] = h;
        sWl[n * 260 + kp] = l;
    }
    __syncthreads();

    const int ar = tid >> 1, asg = tid & 1;
    const int cq = lane & 3, rq = lane >> 2;

    for (int t = 0; t < SS; t++) {
        if (tid == 0) {
            unsigned r;
            do { asm volatile("ld.acquire.gpu.u32 %0, [%1];" : "=r"(r) : "l"(&g_release)); }
            while (r < (unsigned)t);
        }
        __syncthreads();

        int cnt0 = g_cnt0[t];
        int Mc = cell ? (128 - cnt0) : cnt0;
        int base = cell ? cnt0 : 0;
        if (tid < 128) permS[tid] = (tid < Mc) ? g_perm[t * 128 + base + tid] : 0;
        __syncthreads();
        const int Mpad = (Mc + 15) & ~15;
        const int rp = (t & 1) ^ 1;
        const bool act = (w * 16) < Mc;
        const bool ald = ar < Mpad;
        const int ab = permS[ar];
        const float* hbase = g_h + (size_t)rp * (BB * HH) + (size_t)ab * HH;

        float d[4][4];
#pragma unroll
        for (int a = 0; a < 4; a++)
#pragma unroll
            for (int b = 0; b < 4; b++) d[a][b] = 0.f;

        float4 va[4];
        if (ald) {
            const float4* p = (const float4*)(hbase + asg * 16);
            va[0] = __ldcg(p); va[1] = __ldcg(p + 1); va[2] = __ldcg(p + 2); va[3] = __ldcg(p + 3);
        }
        for (int ks = 0; ks < 16; ks++) {
            int buf = ks & 1;
            if (ald) {
                uint32_t h0, l0, h1, l1;
#pragma unroll
                for (int i = 0; i < 4; i++) {
                    split2(va[i].x, va[i].y, h0, l0);
                    split2(va[i].z, va[i].w, h1, l1);
                    int ai = buf * 2560 + ar * 20 + asg * 8 + i * 2;
                    sAh[ai] = h0; sAh[ai + 1] = h1;
                    sAl[ai] = l0; sAl[ai + 1] = l1;
                }
            }
            __syncthreads();
            if (ks < 15 && ald) {
                const float4* p = (const float4*)(hbase + (ks + 1) * 32 + asg * 16);
                va[0] = __ldcg(p); va[1] = __ldcg(p + 1); va[2] = __ldcg(p + 2); va[3] = __ldcg(p + 3);
            }
            if (act) {
                const uint32_t* Ah = sAh + buf * 2560;
                const uint32_t* Al = sAl + buf * 2560;
                const int r0 = w * 16 + rq;
#pragma unroll
                for (int kc = 0; kc < 2; kc++) {
                    int kb = kc * 8 + cq;
                    int kg = ks * 16 + kb;
                    uint32_t ah0 = Ah[r0 * 20 + kb],     ah1 = Ah[(r0 + 8) * 20 + kb];
                    uint32_t ah2 = Ah[r0 * 20 + kb + 4], ah3 = Ah[(r0 + 8) * 20 + kb + 4];
                    uint32_t al0 = Al[r0 * 20 + kb],     al1 = Al[(r0 + 8) * 20 + kb];
                    uint32_t al2 = Al[r0 * 20 + kb + 4], al3 = Al[(r0 + 8) * 20 + kb + 4];
#pragma unroll
                    for (int nt = 0; nt < 4; nt++) {
                        int n = nt * 8 + rq;
                        uint32_t bh0 = sWh[n * 260 + kg], bh1 = sWh[n * 260 + kg + 4];
                        uint32_t bl0 = sWl[n * 260 + kg], bl1 = sWl[n * 260 + kg + 4];
                        mma16(d[nt], ah0, ah1, ah2, ah3, bh0, bh1);
                        mma16(d[nt], ah0, ah1, ah2, ah3, bl0, bl1);
                        mma16(d[nt], al0, al1, al2, al3, bh0, bh1);
                    }
                }
            }
        }

        if (act) {
            int wp = t & 1;
#pragma unroll
            for (int half = 0; half < 2; half++) {
                int rm = w * 16 + rq + half * 8;
                if (rm < Mc) {
                    int b = permS[rm];
                    int jj = j0 + cq * 2;
                    size_t xb = ((size_t)(t * 128 + b)) * GG + jj;
                    float2 xi = *(const float2*)(g_xg + xb);
                    float2 xf = *(const float2*)(g_xg + xb + 512);
                    float2 xg = *(const float2*)(g_xg + xb + 1024);
                    float2 xo = *(const float2*)(g_xg + xb + 1536);
                    float2 cc = __ldcg((const float2*)(g_c + b * HH + jj));
                    float i0 = sigm(xi.x + d[0][half * 2]);
                    float i1 = sigm(xi.y + d[0][half * 2 + 1]);
                    float f0 = sigm(xf.x + d[1][half * 2]);
                    float f1 = sigm(xf.y + d[1][half * 2 + 1]);
                    float gg0 = tanh_fast(xg.x + d[2][half * 2]);
                    float gg1 = tanh_fast(xg.y + d[2][half * 2 + 1]);
                    float o0 = sigm(xo.x + d[3][half * 2]);
                    float o1 = sigm(xo.y + d[3][half * 2 + 1]);
                    float c0 = f0 * cc.x + i0 * gg0;
                    float c1 = f1 * cc.y + i1 * gg1;
                    float h0 = o0 * tanh_fast(c0);
                    float h1 = o1 * tanh_fast(c1);
                    *(float2*)(g_c + b * HH + jj) = make_float2(c0, c1);
                    *(float2*)(g_h + (size_t)wp * (BB * HH) + b * HH + jj) = make_float2(h0, h1);
                    *(float2*)(out + (size_t)b * (SS * HH) + t * HH + jj) = make_float2(h0, h1);
                }
            }
        }
        __threadfence();
        __syncthreads();
        if (tid == 0) {
            unsigned v = atomicAdd(&g_count, 1u) + 1u;
            if (v == 128u * (unsigned)(t + 1)) {
                asm volatile("st.release.gpu.u32 [%0], %1;" :: "l"(&g_release), "r"((unsigned)(t + 1)));
            }
        }
    }
}

__global__ void k_tail(float* __restrict__ out) {
    int i = blockIdx.x * 256 + threadIdx.x;
    if (i < BB * HH) {
        out[(size_t)BSH + i] = g_h[BB * HH + i];            // h_last (t=1023, parity 1)
        out[(size_t)BSH + BB * HH + i] = g_c[i];            // c_last
    }
}

extern "C" void kernel_launch(void* const* d_in, const int* in_sizes, int n_in,
                              void* d_out, int out_size) {
    const int*   inp   = (const int*)d_in[0];
    const float* embed = (const float*)d_in[1];
    const float* Wih   = (const float*)d_in[2];
    const float* Whh   = (const float*)d_in[3];
    const float* bih   = (const float*)d_in[4];
    const float* bhh   = (const float*)d_in[5];
    float* out = (float*)d_out;

    cudaFuncSetAttribute(k_phase1, cudaFuncAttributeMaxDynamicSharedMemorySize, SMEM1);
    cudaFuncSetAttribute(k_phase2, cudaFuncAttributeMaxDynamicSharedMemorySize, SMEM2);

    k_init<<<512, 256>>>(bih, bhh);
    k_setup<<<1, 1024>>>(inp);
    k_phase1<<<dim3(32, 1025), 256, SMEM1>>>(embed, Wih);
    k_phase2<<<128, 256, SMEM2>>>(Whh, out);
    if (out_size >= BSH + 2 * BB * HH) k_tail<<<256, 256>>>(out);
}